// round 16
// baseline (speedup 1.0000x reference)
#include <cuda_runtime.h>
#include <math.h>
#include <stdint.h>

#define B_ 2
#define S_ 4096
#define D_ 768
#define H_ 12
#define DK_ 64

// scratch (no cudaMalloc allowed)
__device__ float g_Q[(size_t)B_ * S_ * D_];
__device__ float g_K[(size_t)B_ * S_ * D_];
__device__ float g_V[(size_t)B_ * S_ * D_];
__device__ float g_AO[(size_t)B_ * S_ * D_];
__device__ float g_T[(size_t)3 * B_ * S_ * D_];   // pre-rounded, k-permuted inputs
__device__ float g_W4[(size_t)4 * D_ * D_];       // pre-rounded, k-permuted weights

__device__ __forceinline__ uint32_t f2tf(float x) {
    uint32_t u;
    asm("cvt.rna.tf32.f32 %0, %1;" : "=r"(u) : "f"(x));
    return u;
}

__device__ __forceinline__ void mma8(float* c, const uint32_t* a,
                                     uint32_t b0, uint32_t b1) {
    asm volatile(
        "mma.sync.aligned.m16n8k8.row.col.f32.tf32.tf32.f32 "
        "{%0,%1,%2,%3}, {%4,%5,%6,%7}, {%8,%9}, {%0,%1,%2,%3};"
        : "+f"(c[0]), "+f"(c[1]), "+f"(c[2]), "+f"(c[3])
        : "r"(a[0]), "r"(a[1]), "r"(a[2]), "r"(a[3]), "r"(b0), "r"(b1));
}

__device__ __forceinline__ void cpa16(uint32_t saddr, const void* g) {
    asm volatile("cp.async.cg.shared.global [%0], [%1], 16;"
                 :: "r"(saddr), "l"(g));
}
__device__ __forceinline__ uint32_t cvs(const void* p) {
    return (uint32_t)__cvta_generic_to_shared(p);
}
#define CPCOMMIT asm volatile("cp.async.commit_group;")
#define CPWAIT0  asm volatile("cp.async.wait_group 0;")

// ---------------------------------------------------------------------------
// batched pre-round to tf32 AND permute within 8-elem groups of last dim:
// out[2*(k&3)+(k>>2)] = in[k]  ->  {in0,in4,in1,in5,in2,in6,in3,in7}
// ---------------------------------------------------------------------------
__global__ void preround3(const float* __restrict__ s0,
                          const float* __restrict__ s1,
                          const float* __restrict__ s2,
                          float* __restrict__ dst, int n8) {
    int i = blockIdx.x * blockDim.x + threadIdx.x;
    if (i >= n8) return;
    const float* src = (blockIdx.y == 0) ? s0 : (blockIdx.y == 1) ? s1 : s2;
    float4 lo = ((const float4*)src)[2 * i];
    float4 hi = ((const float4*)src)[2 * i + 1];
    uint4 o0, o1;
    o0.x = f2tf(lo.x); o0.y = f2tf(hi.x); o0.z = f2tf(lo.y); o0.w = f2tf(hi.y);
    o1.x = f2tf(lo.z); o1.y = f2tf(hi.z); o1.z = f2tf(lo.w); o1.w = f2tf(hi.w);
    uint4* d = (uint4*)(dst + (size_t)blockIdx.y * n8 * 8);
    d[2 * i] = o0;
    d[2 * i + 1] = o1;
}

__global__ void preround4(const float* __restrict__ s0,
                          const float* __restrict__ s1,
                          const float* __restrict__ s2,
                          const float* __restrict__ s3,
                          float* __restrict__ dst, int n8) {
    int i = blockIdx.x * blockDim.x + threadIdx.x;
    if (i >= n8) return;
    const float* src = (blockIdx.y == 0) ? s0 : (blockIdx.y == 1) ? s1
                     : (blockIdx.y == 2) ? s2 : s3;
    float4 lo = ((const float4*)src)[2 * i];
    float4 hi = ((const float4*)src)[2 * i + 1];
    uint4 o0, o1;
    o0.x = f2tf(lo.x); o0.y = f2tf(hi.x); o0.z = f2tf(lo.y); o0.w = f2tf(hi.y);
    o1.x = f2tf(lo.z); o1.y = f2tf(hi.z); o1.z = f2tf(lo.w); o1.w = f2tf(hi.w);
    uint4* d = (uint4*)(dst + (size_t)blockIdx.y * n8 * 8);
    d[2 * i] = o0;
    d[2 * i + 1] = o1;
}

// ---------------------------------------------------------------------------
// Fused QKV TC GEMM on k-permuted operands: LDS64 pair fragments, stride 72.
// 128x64 tile, 8 warps (4m x 2n), cp.async double-buffered, k-tile 64.
// z==0 (Q): tf32(0.125*v), head-dim PERMUTED out; z==1 (K): tf32(v), PERMUTED;
// z==2 (V): tf32(v), unpermuted.
// ---------------------------------------------------------------------------
#define GSTR 72

__global__ void __launch_bounds__(256) gemm_qkv(
        const float* __restrict__ T, const float* __restrict__ W4,
        const float* __restrict__ bq, const float* __restrict__ bk,
        const float* __restrict__ bv,
        float* __restrict__ Qp, float* __restrict__ Kp, float* __restrict__ Vp) {
    extern __shared__ float sg[];
    float* Asb[2] = { sg,          sg + 128 * GSTR };          // 128*72 each
    float* Wsb[2] = { sg + 2 * 128 * GSTR,
                      sg + 2 * 128 * GSTR + 64 * GSTR };       // 64*72 each

    const int M = B_ * S_, N = D_, K = D_;
    const int z = blockIdx.z;
    const float* A = T + (size_t)z * M * K;
    const float* W = W4 + (size_t)z * N * K;
    const float* bias = (z == 0) ? bq : (z == 1) ? bk : bv;
    float* C = (z == 0) ? Qp : (z == 1) ? Kp : Vp;

    const int tid = threadIdx.x, lane = tid & 31, w = tid >> 5;
    const int mw = w >> 1, nw = w & 1, g = lane >> 2, t = lane & 3;
    const int m0 = blockIdx.x * 128, n0 = blockIdx.y * 64;

    float acc[2][4][4] = {};

#define GSTAGE(k0, bufi)                                                       \
    {                                                                          \
        _Pragma("unroll")                                                      \
        for (int r = 0; r < 8; r++) {                                          \
            int idx = tid + r * 256, rr = idx >> 4, cc = idx & 15;             \
            cpa16(cvs(&Asb[bufi][rr * GSTR + cc * 4]),                         \
                  &A[(size_t)(m0 + rr) * K + (k0) + cc * 4]);                  \
        }                                                                      \
        _Pragma("unroll")                                                      \
        for (int r = 0; r < 4; r++) {                                          \
            int idx = tid + r * 256, rr = idx >> 4, cc = idx & 15;             \
            cpa16(cvs(&Wsb[bufi][rr * GSTR + cc * 4]),                         \
                  &W[(size_t)(n0 + rr) * K + (k0) + cc * 4]);                  \
        }                                                                      \
    }

    GSTAGE(0, 0); CPCOMMIT;
    const int NT = K / 64;
    for (int kt = 0; kt < NT; kt++) {
        CPWAIT0;
        __syncthreads();
        if (kt + 1 < NT) { GSTAGE((kt + 1) * 64, (kt + 1) & 1); CPCOMMIT; }
        const uint32_t* Au = (const uint32_t*)Asb[kt & 1];
        const uint32_t* Wu = (const uint32_t*)Wsb[kt & 1];
#pragma unroll
        for (int k8 = 0; k8 < 8; k8++) {
            uint32_t a[2][4];
#pragma unroll
            for (int mm = 0; mm < 2; mm++) {
                int ar = (mw * 32 + mm * 16 + g) * GSTR + 2 * t + 8 * k8;
                uint2 a02 = *(const uint2*)&Au[ar];
                uint2 a13 = *(const uint2*)&Au[ar + 8 * GSTR];
                a[mm][0] = a02.x; a[mm][1] = a13.x;
                a[mm][2] = a02.y; a[mm][3] = a13.y;
            }
#pragma unroll
            for (int nf = 0; nf < 4; nf++) {
                int br = (nw * 32 + nf * 8 + g) * GSTR + 2 * t + 8 * k8;
                uint2 bb = *(const uint2*)&Wu[br];
                mma8(acc[0][nf], a[0], bb.x, bb.y);
                mma8(acc[1][nf], a[1], bb.x, bb.y);
            }
        }
    }

    const float sc = (z == 0) ? 0.125f : 1.0f;
    const bool perm = (z < 2);
#pragma unroll
    for (int mm = 0; mm < 2; mm++) {
        int mrow = m0 + mw * 32 + mm * 16 + g;
#pragma unroll
        for (int nf = 0; nf < 4; nf++) {
            int base8 = n0 + nw * 32 + nf * 8;
            float b0 = bias[base8 + 2 * t], b1 = bias[base8 + 2 * t + 1];
            float v0 = __uint_as_float(f2tf((acc[mm][nf][0] + b0) * sc));
            float v1 = __uint_as_float(f2tf((acc[mm][nf][1] + b1) * sc));
            float v2 = __uint_as_float(f2tf((acc[mm][nf][2] + b0) * sc));
            float v3 = __uint_as_float(f2tf((acc[mm][nf][3] + b1) * sc));
            if (perm) {
                int p0 = base8 + (t & 1) * 4 + (t >> 1);  // perm(2t)
                C[(size_t)mrow * N + p0]     = v0;
                C[(size_t)mrow * N + p0 + 2] = v1;        // perm(2t+1)
                C[(size_t)(mrow + 8) * N + p0]     = v2;
                C[(size_t)(mrow + 8) * N + p0 + 2] = v3;
            } else {
                int n = base8 + 2 * t;
                *(float2*)&C[(size_t)mrow * N + n] = make_float2(v0, v1);
                *(float2*)&C[(size_t)(mrow + 8) * N + n] = make_float2(v2, v3);
            }
        }
    }
}

// ---------------------------------------------------------------------------
// O-projection GEMM (k-permuted operands, raw fp32 out, streaming store).
// ---------------------------------------------------------------------------
__global__ void __launch_bounds__(256) gemm_o(const float* __restrict__ A,
                                              const float* __restrict__ W,
                                              const float* __restrict__ bias,
                                              float* __restrict__ C,
                                              int M, int N, int K) {
    extern __shared__ float sg[];
    float* Asb[2] = { sg,          sg + 128 * GSTR };
    float* Wsb[2] = { sg + 2 * 128 * GSTR,
                      sg + 2 * 128 * GSTR + 64 * GSTR };

    const int tid = threadIdx.x, lane = tid & 31, w = tid >> 5;
    const int mw = w >> 1, nw = w & 1, g = lane >> 2, t = lane & 3;
    const int m0 = blockIdx.x * 128, n0 = blockIdx.y * 64;

    float acc[2][4][4] = {};

    GSTAGE(0, 0); CPCOMMIT;
    const int NT = K / 64;
    for (int kt = 0; kt < NT; kt++) {
        CPWAIT0;
        __syncthreads();
        if (kt + 1 < NT) { GSTAGE((kt + 1) * 64, (kt + 1) & 1); CPCOMMIT; }
        const uint32_t* Au = (const uint32_t*)Asb[kt & 1];
        const uint32_t* Wu = (const uint32_t*)Wsb[kt & 1];
#pragma unroll
        for (int k8 = 0; k8 < 8; k8++) {
            uint32_t a[2][4];
#pragma unroll
            for (int mm = 0; mm < 2; mm++) {
                int ar = (mw * 32 + mm * 16 + g) * GSTR + 2 * t + 8 * k8;
                uint2 a02 = *(const uint2*)&Au[ar];
                uint2 a13 = *(const uint2*)&Au[ar + 8 * GSTR];
                a[mm][0] = a02.x; a[mm][1] = a13.x;
                a[mm][2] = a02.y; a[mm][3] = a13.y;
            }
#pragma unroll
            for (int nf = 0; nf < 4; nf++) {
                int br = (nw * 32 + nf * 8 + g) * GSTR + 2 * t + 8 * k8;
                uint2 bb = *(const uint2*)&Wu[br];
                mma8(acc[0][nf], a[0], bb.x, bb.y);
                mma8(acc[1][nf], a[1], bb.x, bb.y);
            }
        }
    }

#pragma unroll
    for (int mm = 0; mm < 2; mm++) {
        int mrow = m0 + mw * 32 + mm * 16 + g;
#pragma unroll
        for (int nf = 0; nf < 4; nf++) {
            int n = n0 + nw * 32 + nf * 8 + 2 * t;
            float b0 = bias[n], b1 = bias[n + 1];
            __stcs((float2*)&C[(size_t)mrow * N + n],
                   make_float2(acc[mm][nf][0] + b0, acc[mm][nf][1] + b1));
            __stcs((float2*)&C[(size_t)(mrow + 8) * N + n],
                   make_float2(acc[mm][nf][2] + b0, acc[mm][nf][3] + b1));
        }
    }
}

// ---------------------------------------------------------------------------
// TC flash attention — R15 VERBATIM except AO epilogue writes feature-
// permuted values (to match the k-permuted Wo in gemm_o).
// ---------------------------------------------------------------------------
#define STRK 72
#define STRV 72

__global__ void __launch_bounds__(256, 2)
attn_tc(const float* __restrict__ Qg, const float* __restrict__ Kg,
        const float* __restrict__ Vg, float* __restrict__ Pout,
        float* __restrict__ Oout) {
    extern __shared__ float sm[];
    float* Ksb[2] = { sm,                 sm + 64 * STRK };
    float* Vsb[2] = { sm + 2 * 64 * STRK, sm + 2 * 64 * STRK + 64 * STRV };
    float* Qs = sm + 2 * 64 * STRK + 2 * 64 * STRV;  // 64*72 = 4608 (Q / PT)
    uint2* PT = (uint2*)Qs;                          // P: [col*36 + pair]
    float* Ls = Qs + 4608;                           // 256 floats
    const uint32_t* Qu = (const uint32_t*)Qs;

    const int tid = threadIdx.x, lane = tid & 31, w = tid >> 5;
    const int mw = w & 1, nw = w >> 1, g = lane >> 2, t = lane & 3;
    const int q0 = blockIdx.x * 64, h = blockIdx.y, b = blockIdx.z;
    const size_t qbase = ((size_t)b * S_ + q0) * D_ + h * DK_;
    const size_t kvbase = (size_t)b * S_ * D_ + h * DK_;

#define KSTAGE(jt, bufi)                                                       \
    {                                                                          \
        _Pragma("unroll")                                                      \
        for (int r = 0; r < 4; r++) {                                          \
            int idx = tid + r * 256, rr = idx >> 4, cc = idx & 15;             \
            cpa16(cvs(&Ksb[bufi][rr * STRK + cc * 4]),                         \
                  &Kg[kvbase + (size_t)((jt) * 64 + rr) * D_ + cc * 4]);       \
        }                                                                      \
    }
#define VSTAGE(jt, bufi)                                                       \
    {                                                                          \
        _Pragma("unroll")                                                      \
        for (int r = 0; r < 4; r++) {                                          \
            int idx = tid + r * 256, rr = idx >> 4, cc = idx & 15;             \
            cpa16(cvs(&Vsb[bufi][rr * STRV + cc * 4]),                         \
                  &Vg[kvbase + (size_t)((jt) * 64 + rr) * D_ + cc * 4]);       \
        }                                                                      \
    }

    // stage Q (tf32, scaled, head-dim permuted); pull A-fragments via LDS64
#pragma unroll
    for (int r = 0; r < 4; r++) {
        int idx = tid + r * 256, rr = idx >> 4, cc = idx & 15;
        *(float4*)&Qs[rr * STRK + cc * 4] =
            *(const float4*)&Qg[qbase + (size_t)rr * D_ + cc * 4];
    }
    __syncthreads();
    uint32_t qa[2][8][4];
#pragma unroll
    for (int mm = 0; mm < 2; mm++) {
        int ar = (mw * 32 + mm * 16 + g) * STRK + 2 * t;
#pragma unroll
        for (int k8 = 0; k8 < 8; k8++) {
            uint2 q02 = *(const uint2*)&Qu[ar + 8 * k8];
            uint2 q13 = *(const uint2*)&Qu[ar + 8 * STRK + 8 * k8];
            qa[mm][k8][0] = q02.x; qa[mm][k8][1] = q13.x;
            qa[mm][k8][2] = q02.y; qa[mm][k8][3] = q13.y;
        }
    }

    // ---------------- pass 1: rowsums of exp(scores) ----------------
    KSTAGE(0, 0); CPCOMMIT;
    float ls[2][2] = {};
    for (int jt = 0; jt < S_ / 64; jt++) {
        CPWAIT0;
        __syncthreads();
        if (jt + 1 < S_ / 64) { KSTAGE(jt + 1, (jt + 1) & 1); CPCOMMIT; }
        const uint32_t* Ku = (const uint32_t*)Ksb[jt & 1];
        float c[2][2][4] = {};
#pragma unroll
        for (int k8 = 0; k8 < 8; k8++) {
#pragma unroll
            for (int nf = 0; nf < 2; nf++) {
                int br = (nw * 16 + nf * 8 + g) * STRK + 2 * t + 8 * k8;
                uint2 bb = *(const uint2*)&Ku[br];
                mma8(c[0][nf], qa[0][k8], bb.x, bb.y);
                mma8(c[1][nf], qa[1][k8], bb.x, bb.y);
            }
        }
#pragma unroll
        for (int mm = 0; mm < 2; mm++)
#pragma unroll
            for (int nf = 0; nf < 2; nf++) {
                ls[mm][0] += __expf(c[mm][nf][0]) + __expf(c[mm][nf][1]);
                ls[mm][1] += __expf(c[mm][nf][2]) + __expf(c[mm][nf][3]);
            }
    }
#pragma unroll
    for (int mm = 0; mm < 2; mm++)
#pragma unroll
        for (int hh = 0; hh < 2; hh++) {
            ls[mm][hh] += __shfl_xor_sync(~0u, ls[mm][hh], 1);
            ls[mm][hh] += __shfl_xor_sync(~0u, ls[mm][hh], 2);
        }
    if (t == 0) {
#pragma unroll
        for (int mm = 0; mm < 2; mm++) {
            Ls[nw * 64 + mw * 32 + mm * 16 + g]     = ls[mm][0];
            Ls[nw * 64 + mw * 32 + mm * 16 + 8 + g] = ls[mm][1];
        }
    }
    KSTAGE(0, 0); VSTAGE(0, 0); CPCOMMIT;
    __syncthreads();
    float linv[2][2];
#pragma unroll
    for (int mm = 0; mm < 2; mm++) {
        int r0 = mw * 32 + mm * 16 + g;
        linv[mm][0] = 1.f / (Ls[r0] + Ls[64 + r0] + Ls[128 + r0] + Ls[192 + r0]);
        int r1 = r0 + 8;
        linv[mm][1] = 1.f / (Ls[r1] + Ls[64 + r1] + Ls[128 + r1] + Ls[192 + r1]);
    }
    __syncthreads();  // Qs fragments consumed; PT region now owned by pass 2

    // ---------------- pass 2: P out + P@V ----------------
    float out[2][2][4] = {};
    for (int jt = 0; jt < S_ / 64; jt++) {
        CPWAIT0;
        __syncthreads();
        if (jt + 1 < S_ / 64) {
            KSTAGE(jt + 1, (jt + 1) & 1); VSTAGE(jt + 1, (jt + 1) & 1); CPCOMMIT;
        }
        const uint32_t* Ku = (const uint32_t*)Ksb[jt & 1];
        const uint32_t* Vu = (const uint32_t*)Vsb[jt & 1];
        float c[2][2][4] = {};
#pragma unroll
        for (int k8 = 0; k8 < 8; k8++) {
#pragma unroll
            for (int nf = 0; nf < 2; nf++) {
                int br = (nw * 16 + nf * 8 + g) * STRK + 2 * t + 8 * k8;
                uint2 bb = *(const uint2*)&Ku[br];
                mma8(c[0][nf], qa[0][k8], bb.x, bb.y);
                mma8(c[1][nf], qa[1][k8], bb.x, bb.y);
            }
        }
        // normalized P -> gmem (streaming); tf32 P -> transposed smem tile
#pragma unroll
        for (int mm = 0; mm < 2; mm++) {
            int rowg = mw * 32 + mm * 16 + g;
            int pi = 16 * mw + 8 * mm + g;
            size_t gp = ((size_t)(b * H_ + h) * S_ + (q0 + rowg)) * S_ +
                        jt * 64 + nw * 16 + 2 * t;
#pragma unroll
            for (int nf = 0; nf < 2; nf++) {
                float p0 = __expf(c[mm][nf][0]) * linv[mm][0];
                float p1 = __expf(c[mm][nf][1]) * linv[mm][0];
                float p2 = __expf(c[mm][nf][2]) * linv[mm][1];
                float p3 = __expf(c[mm][nf][3]) * linv[mm][1];
                __stcs((float2*)&Pout[gp + nf * 8], make_float2(p0, p1));
                __stcs((float2*)&Pout[gp + nf * 8 + (size_t)8 * S_],
                       make_float2(p2, p3));
                int c0 = nw * 16 + nf * 8 + 2 * t;
                PT[c0 * 36 + pi] = make_uint2(f2tf(p0), f2tf(p2));
                PT[(c0 + 1) * 36 + pi] = make_uint2(f2tf(p1), f2tf(p3));
            }
        }
        __syncthreads();
        // P @ V  (pa via conflict-free LDS64)
#pragma unroll
        for (int k8 = 0; k8 < 8; k8++) {
            int ca = t + 8 * k8, cb = ca + 4;
            uint2 u0 = PT[ca * 36 + 16 * mw + g];
            uint2 u1 = PT[cb * 36 + 16 * mw + g];
            uint2 u2 = PT[ca * 36 + 16 * mw + 8 + g];
            uint2 u3 = PT[cb * 36 + 16 * mw + 8 + g];
            uint32_t pa0[4] = { u0.x, u0.y, u1.x, u1.y };
            uint32_t pa1[4] = { u2.x, u2.y, u3.x, u3.y };
#pragma unroll
            for (int nf = 0; nf < 2; nf++) {
                int n = nw * 16 + nf * 8 + g;
                uint32_t b0 = Vu[(8 * k8 + t) * STRV + n];
                uint32_t b1 = Vu[(8 * k8 + t + 4) * STRV + n];
                mma8(out[0][nf], pa0, b0, b1);
                mma8(out[1][nf], pa1, b0, b1);
            }
        }
        __syncthreads();
    }

    // epilogue: AO in [B,S,D], tf32-rounded AND feature-permuted for gemm_o
#pragma unroll
    for (int mm = 0; mm < 2; mm++) {
        int row = q0 + mw * 32 + mm * 16 + g;
#pragma unroll
        for (int nf = 0; nf < 2; nf++) {
            int base8 = h * DK_ + nw * 16 + nf * 8;
            int p0 = base8 + (t & 1) * 4 + (t >> 1);  // perm(2t)
            size_t r0 = ((size_t)b * S_ + row) * D_;
            size_t r1 = ((size_t)b * S_ + row + 8) * D_;
            Oout[r0 + p0]     = __uint_as_float(f2tf(out[mm][nf][0]));
            Oout[r0 + p0 + 2] = __uint_as_float(f2tf(out[mm][nf][1]));
            Oout[r1 + p0]     = __uint_as_float(f2tf(out[mm][nf][2]));
            Oout[r1 + p0 + 2] = __uint_as_float(f2tf(out[mm][nf][3]));
        }
    }
}

// ---------------------------------------------------------------------------
extern "C" void kernel_launch(void* const* d_in, const int* in_sizes, int n_in,
                              void* d_out, int out_size) {
    const float* query = (const float*)d_in[0];
    const float* key   = (const float*)d_in[1];
    const float* value = (const float*)d_in[2];
    const float* Wq = (const float*)d_in[3];
    const float* bq = (const float*)d_in[4];
    const float* Wk = (const float*)d_in[5];
    const float* bk = (const float*)d_in[6];
    const float* Wv = (const float*)d_in[7];
    const float* bv = (const float*)d_in[8];
    const float* Wo = (const float*)d_in[9];
    const float* bo = (const float*)d_in[10];

    float* out_main = (float*)d_out;
    float* out_attn = (float*)d_out + (size_t)B_ * S_ * D_;

    float* Qp;  cudaGetSymbolAddress((void**)&Qp, g_Q);
    float* Kp;  cudaGetSymbolAddress((void**)&Kp, g_K);
    float* Vp;  cudaGetSymbolAddress((void**)&Vp, g_V);
    float* AOp; cudaGetSymbolAddress((void**)&AOp, g_AO);
    float* Tp;  cudaGetSymbolAddress((void**)&Tp, g_T);
    float* Wp;  cudaGetSymbolAddress((void**)&Wp, g_W4);

    const size_t NX = (size_t)B_ * S_ * D_;   // 6291456
    const size_t NW = (size_t)D_ * D_;        // 589824

    preround3<<<dim3((int)(NX / 8 + 255) / 256, 3), 256>>>(
        query, key, value, Tp, (int)(NX / 8));
    preround4<<<dim3((int)(NW / 8 + 255) / 256, 4), 256>>>(
        Wq, Wk, Wv, Wo, Wp, (int)(NW / 8));

    const int M = B_ * S_;
    const int gsmem = (2 * 128 * GSTR + 2 * 64 * GSTR) * 4;   // 110592 B
    cudaFuncSetAttribute(gemm_qkv,
                         cudaFuncAttributeMaxDynamicSharedMemorySize, gsmem);
    cudaFuncSetAttribute(gemm_o,
                         cudaFuncAttributeMaxDynamicSharedMemorySize, gsmem);
    const int asmem = (2 * 64 * STRK + 2 * 64 * STRV + 4608 + 256) * 4;  // 93184 B
    cudaFuncSetAttribute(attn_tc,
                         cudaFuncAttributeMaxDynamicSharedMemorySize, asmem);

    gemm_qkv<<<dim3(M / 128, D_ / 64, 3), 256, gsmem>>>(
        Tp, Wp, bq, bk, bv, Qp, Kp, Vp);

    attn_tc<<<dim3(S_ / 64, H_, B_), 256, asmem>>>(Qp, Kp, Vp, out_attn, AOp);

    gemm_o<<<dim3(M / 128, D_ / 64), 256, gsmem>>>(
        AOp, Wp + 3 * NW, bo, out_main, M, D_, D_);
}

// round 17
// speedup vs baseline: 1.5400x; 1.5400x over previous
#include <cuda_runtime.h>
#include <math.h>
#include <stdint.h>

#define B_ 2
#define S_ 4096
#define D_ 768
#define H_ 12
#define DK_ 64

// scratch (no cudaMalloc allowed)
__device__ float g_Q[(size_t)B_ * S_ * D_];
__device__ float g_K[(size_t)B_ * S_ * D_];
__device__ float g_V[(size_t)B_ * S_ * D_];
__device__ float g_AO[(size_t)B_ * S_ * D_];
__device__ float g_T[(size_t)3 * B_ * S_ * D_];   // pre-rounded, k-permuted inputs
__device__ float g_W4[(size_t)4 * D_ * D_];       // Wq/Wk/Wv k-permuted; Wo plain

__device__ __forceinline__ uint32_t f2tf(float x) {
    uint32_t u;
    asm("cvt.rna.tf32.f32 %0, %1;" : "=r"(u) : "f"(x));
    return u;
}

__device__ __forceinline__ void mma8(float* c, const uint32_t* a,
                                     uint32_t b0, uint32_t b1) {
    asm volatile(
        "mma.sync.aligned.m16n8k8.row.col.f32.tf32.tf32.f32 "
        "{%0,%1,%2,%3}, {%4,%5,%6,%7}, {%8,%9}, {%0,%1,%2,%3};"
        : "+f"(c[0]), "+f"(c[1]), "+f"(c[2]), "+f"(c[3])
        : "r"(a[0]), "r"(a[1]), "r"(a[2]), "r"(a[3]), "r"(b0), "r"(b1));
}

__device__ __forceinline__ void cpa16(uint32_t saddr, const void* g) {
    asm volatile("cp.async.cg.shared.global [%0], [%1], 16;"
                 :: "r"(saddr), "l"(g));
}
__device__ __forceinline__ uint32_t cvs(const void* p) {
    return (uint32_t)__cvta_generic_to_shared(p);
}
#define CPCOMMIT asm volatile("cp.async.commit_group;")
#define CPWAIT0  asm volatile("cp.async.wait_group 0;")

// ---------------------------------------------------------------------------
// preround3: tf32 + permute within 8-groups (inputs, for QKV pair loads)
// preround4: Wq/Wk/Wv permuted; Wo (y==3) plain tf32
// perm: out[2*(k&3)+(k>>2)] = in[k]
// ---------------------------------------------------------------------------
__global__ void preround3(const float* __restrict__ s0,
                          const float* __restrict__ s1,
                          const float* __restrict__ s2,
                          float* __restrict__ dst, int n8) {
    int i = blockIdx.x * blockDim.x + threadIdx.x;
    if (i >= n8) return;
    const float* src = (blockIdx.y == 0) ? s0 : (blockIdx.y == 1) ? s1 : s2;
    float4 lo = ((const float4*)src)[2 * i];
    float4 hi = ((const float4*)src)[2 * i + 1];
    uint4 o0, o1;
    o0.x = f2tf(lo.x); o0.y = f2tf(hi.x); o0.z = f2tf(lo.y); o0.w = f2tf(hi.y);
    o1.x = f2tf(lo.z); o1.y = f2tf(hi.z); o1.z = f2tf(lo.w); o1.w = f2tf(hi.w);
    uint4* d = (uint4*)(dst + (size_t)blockIdx.y * n8 * 8);
    d[2 * i] = o0;
    d[2 * i + 1] = o1;
}

__global__ void preround4(const float* __restrict__ s0,
                          const float* __restrict__ s1,
                          const float* __restrict__ s2,
                          const float* __restrict__ s3,
                          float* __restrict__ dst, int n8) {
    int i = blockIdx.x * blockDim.x + threadIdx.x;
    if (i >= n8) return;
    const float* src = (blockIdx.y == 0) ? s0 : (blockIdx.y == 1) ? s1
                     : (blockIdx.y == 2) ? s2 : s3;
    float4 lo = ((const float4*)src)[2 * i];
    float4 hi = ((const float4*)src)[2 * i + 1];
    uint4 o0, o1;
    if (blockIdx.y < 3) {  // permuted
        o0.x = f2tf(lo.x); o0.y = f2tf(hi.x); o0.z = f2tf(lo.y); o0.w = f2tf(hi.y);
        o1.x = f2tf(lo.z); o1.y = f2tf(hi.z); o1.z = f2tf(lo.w); o1.w = f2tf(hi.w);
    } else {               // Wo: plain
        o0.x = f2tf(lo.x); o0.y = f2tf(lo.y); o0.z = f2tf(lo.z); o0.w = f2tf(lo.w);
        o1.x = f2tf(hi.x); o1.y = f2tf(hi.y); o1.z = f2tf(hi.z); o1.w = f2tf(hi.w);
    }
    uint4* d = (uint4*)(dst + (size_t)blockIdx.y * n8 * 8);
    d[2 * i] = o0;
    d[2 * i + 1] = o1;
}

// ---------------------------------------------------------------------------
// Fused QKV TC GEMM, k-permuted operands, LDS64 pair fragments, stride 72,
// k-tile 32 double-buffered (smem 55 KB -> 2 blocks/SM preserved).
// z==0 (Q): tf32(0.125*v), head-dim PERMUTED out; z==1 (K): tf32(v), PERMUTED;
// z==2 (V): tf32(v), plain.
// ---------------------------------------------------------------------------
#define GSTR 40   // 32 k-floats padded to 40 (pair-bank 20g'+... check below)

// pair-bank for stride 40: uint2 index row*20 + t'. For A loads: rows
// (mw*32+mm*16+g), addr = row*20 + t + 4*k8 -> bank8 = (20*g + t) mod 16 =
// (4g + t) mod 16, bijection per 16 lanes. Same for W rows. Conflict-free.

__global__ void __launch_bounds__(256) gemm_qkv(
        const float* __restrict__ T, const float* __restrict__ W4,
        const float* __restrict__ bq, const float* __restrict__ bk,
        const float* __restrict__ bv,
        float* __restrict__ Qp, float* __restrict__ Kp, float* __restrict__ Vp) {
    extern __shared__ float sg[];
    float* Asb[2] = { sg,               sg + 128 * GSTR };       // 128*40 each
    float* Wsb[2] = { sg + 2 * 128 * GSTR,
                      sg + 2 * 128 * GSTR + 64 * GSTR };         // 64*40 each

    const int M = B_ * S_, N = D_, K = D_;
    const int z = blockIdx.z;
    const float* A = T + (size_t)z * M * K;
    const float* W = W4 + (size_t)z * N * K;
    const float* bias = (z == 0) ? bq : (z == 1) ? bk : bv;
    float* C = (z == 0) ? Qp : (z == 1) ? Kp : Vp;

    const int tid = threadIdx.x, lane = tid & 31, w = tid >> 5;
    const int mw = w >> 1, nw = w & 1, g = lane >> 2, t = lane & 3;
    const int m0 = blockIdx.x * 128, n0 = blockIdx.y * 64;

    float acc[2][4][4] = {};

#define GSTAGE32(k0, bufi)                                                     \
    {                                                                          \
        _Pragma("unroll")                                                      \
        for (int r = 0; r < 4; r++) {                                          \
            int idx = tid + r * 256, rr = idx >> 3, cc = idx & 7;              \
            cpa16(cvs(&Asb[bufi][rr * GSTR + cc * 4]),                         \
                  &A[(size_t)(m0 + rr) * K + (k0) + cc * 4]);                  \
        }                                                                      \
        _Pragma("unroll")                                                      \
        for (int r = 0; r < 2; r++) {                                          \
            int idx = tid + r * 256, rr = idx >> 3, cc = idx & 7;              \
            cpa16(cvs(&Wsb[bufi][rr * GSTR + cc * 4]),                         \
                  &W[(size_t)(n0 + rr) * K + (k0) + cc * 4]);                  \
        }                                                                      \
    }

    GSTAGE32(0, 0); CPCOMMIT;
    const int NT = K / 32;
    for (int kt = 0; kt < NT; kt++) {
        CPWAIT0;
        __syncthreads();
        if (kt + 1 < NT) { GSTAGE32((kt + 1) * 32, (kt + 1) & 1); CPCOMMIT; }
        const uint32_t* Au = (const uint32_t*)Asb[kt & 1];
        const uint32_t* Wu = (const uint32_t*)Wsb[kt & 1];
#pragma unroll
        for (int k8 = 0; k8 < 4; k8++) {
            uint32_t a[2][4];
#pragma unroll
            for (int mm = 0; mm < 2; mm++) {
                int ar = (mw * 32 + mm * 16 + g) * GSTR + 2 * t + 8 * k8;
                uint2 a02 = *(const uint2*)&Au[ar];
                uint2 a13 = *(const uint2*)&Au[ar + 8 * GSTR];
                a[mm][0] = a02.x; a[mm][1] = a13.x;
                a[mm][2] = a02.y; a[mm][3] = a13.y;
            }
#pragma unroll
            for (int nf = 0; nf < 4; nf++) {
                int br = (nw * 32 + nf * 8 + g) * GSTR + 2 * t + 8 * k8;
                uint2 bb = *(const uint2*)&Wu[br];
                mma8(acc[0][nf], a[0], bb.x, bb.y);
                mma8(acc[1][nf], a[1], bb.x, bb.y);
            }
        }
    }

    const float sc = (z == 0) ? 0.125f : 1.0f;
    const bool perm = (z < 2);
#pragma unroll
    for (int mm = 0; mm < 2; mm++) {
        int mrow = m0 + mw * 32 + mm * 16 + g;
#pragma unroll
        for (int nf = 0; nf < 4; nf++) {
            int base8 = n0 + nw * 32 + nf * 8;
            float b0 = bias[base8 + 2 * t], b1 = bias[base8 + 2 * t + 1];
            float v0 = __uint_as_float(f2tf((acc[mm][nf][0] + b0) * sc));
            float v1 = __uint_as_float(f2tf((acc[mm][nf][1] + b1) * sc));
            float v2 = __uint_as_float(f2tf((acc[mm][nf][2] + b0) * sc));
            float v3 = __uint_as_float(f2tf((acc[mm][nf][3] + b1) * sc));
            if (perm) {
                int p0 = base8 + (t & 1) * 4 + (t >> 1);  // perm(2t)
                C[(size_t)mrow * N + p0]     = v0;
                C[(size_t)mrow * N + p0 + 2] = v1;
                C[(size_t)(mrow + 8) * N + p0]     = v2;
                C[(size_t)(mrow + 8) * N + p0 + 2] = v3;
            } else {
                int n = base8 + 2 * t;
                *(float2*)&C[(size_t)mrow * N + n] = make_float2(v0, v1);
                *(float2*)&C[(size_t)(mrow + 8) * N + n] = make_float2(v2, v3);
            }
        }
    }
}

// ---------------------------------------------------------------------------
// O-projection GEMM — R15 VERBATIM (scalar fragments, stride 68, k-tile 64,
// unpermuted AO and Wo).
// ---------------------------------------------------------------------------
__global__ void __launch_bounds__(256) gemm_o(const float* __restrict__ A,
                                              const float* __restrict__ W,
                                              const float* __restrict__ bias,
                                              float* __restrict__ C,
                                              int M, int N, int K) {
    extern __shared__ float sg[];
    float* Asb[2] = { sg,          sg + 8704 };
    float* Wsb[2] = { sg + 17408,  sg + 17408 + 4352 };

    const int tid = threadIdx.x, lane = tid & 31, w = tid >> 5;
    const int mw = w >> 1, nw = w & 1, g = lane >> 2, t = lane & 3;
    const int m0 = blockIdx.x * 128, n0 = blockIdx.y * 64;

    float acc[2][4][4] = {};

#define GSTAGE(k0, bufi)                                                       \
    {                                                                          \
        _Pragma("unroll")                                                      \
        for (int r = 0; r < 8; r++) {                                          \
            int idx = tid + r * 256, rr = idx >> 4, cc = idx & 15;             \
            cpa16(cvs(&Asb[bufi][rr * 68 + cc * 4]),                           \
                  &A[(size_t)(m0 + rr) * K + (k0) + cc * 4]);                  \
        }                                                                      \
        _Pragma("unroll")                                                      \
        for (int r = 0; r < 4; r++) {                                          \
            int idx = tid + r * 256, rr = idx >> 4, cc = idx & 15;             \
            cpa16(cvs(&Wsb[bufi][rr * 68 + cc * 4]),                           \
                  &W[(size_t)(n0 + rr) * K + (k0) + cc * 4]);                  \
        }                                                                      \
    }

    GSTAGE(0, 0); CPCOMMIT;
    const int NT = K / 64;
    for (int kt = 0; kt < NT; kt++) {
        CPWAIT0;
        __syncthreads();
        if (kt + 1 < NT) { GSTAGE((kt + 1) * 64, (kt + 1) & 1); CPCOMMIT; }
        const uint32_t* Au = (const uint32_t*)Asb[kt & 1];
        const uint32_t* Wu = (const uint32_t*)Wsb[kt & 1];
#pragma unroll
        for (int k8 = 0; k8 < 8; k8++) {
            uint32_t a[2][4];
#pragma unroll
            for (int mm = 0; mm < 2; mm++) {
                int ar = (mw * 32 + mm * 16 + g) * 68 + t + 8 * k8;
                a[mm][0] = Au[ar];     a[mm][1] = Au[ar + 8 * 68];
                a[mm][2] = Au[ar + 4]; a[mm][3] = Au[ar + 8 * 68 + 4];
            }
#pragma unroll
            for (int nf = 0; nf < 4; nf++) {
                int br = (nw * 32 + nf * 8 + g) * 68 + t + 8 * k8;
                uint32_t b0 = Wu[br], b1 = Wu[br + 4];
                mma8(acc[0][nf], a[0], b0, b1);
                mma8(acc[1][nf], a[1], b0, b1);
            }
        }
    }

#pragma unroll
    for (int mm = 0; mm < 2; mm++) {
        int mrow = m0 + mw * 32 + mm * 16 + g;
#pragma unroll
        for (int nf = 0; nf < 4; nf++) {
            int n = n0 + nw * 32 + nf * 8 + 2 * t;
            float b0 = bias[n], b1 = bias[n + 1];
            __stcs((float2*)&C[(size_t)mrow * N + n],
                   make_float2(acc[mm][nf][0] + b0, acc[mm][nf][1] + b1));
            __stcs((float2*)&C[(size_t)(mrow + 8) * N + n],
                   make_float2(acc[mm][nf][2] + b0, acc[mm][nf][3] + b1));
        }
    }
}

// ---------------------------------------------------------------------------
// TC flash attention — R15 VERBATIM (AO epilogue unpermuted float2).
// ---------------------------------------------------------------------------
#define STRK 72
#define STRV 72

__global__ void __launch_bounds__(256, 2)
attn_tc(const float* __restrict__ Qg, const float* __restrict__ Kg,
        const float* __restrict__ Vg, float* __restrict__ Pout,
        float* __restrict__ Oout) {
    extern __shared__ float sm[];
    float* Ksb[2] = { sm,                 sm + 64 * STRK };
    float* Vsb[2] = { sm + 2 * 64 * STRK, sm + 2 * 64 * STRK + 64 * STRV };
    float* Qs = sm + 2 * 64 * STRK + 2 * 64 * STRV;  // 64*72 = 4608 (Q / PT)
    uint2* PT = (uint2*)Qs;                          // P: [col*36 + pair]
    float* Ls = Qs + 4608;                           // 256 floats
    const uint32_t* Qu = (const uint32_t*)Qs;

    const int tid = threadIdx.x, lane = tid & 31, w = tid >> 5;
    const int mw = w & 1, nw = w >> 1, g = lane >> 2, t = lane & 3;
    const int q0 = blockIdx.x * 64, h = blockIdx.y, b = blockIdx.z;
    const size_t qbase = ((size_t)b * S_ + q0) * D_ + h * DK_;
    const size_t kvbase = (size_t)b * S_ * D_ + h * DK_;

#define KSTAGE(jt, bufi)                                                       \
    {                                                                          \
        _Pragma("unroll")                                                      \
        for (int r = 0; r < 4; r++) {                                          \
            int idx = tid + r * 256, rr = idx >> 4, cc = idx & 15;             \
            cpa16(cvs(&Ksb[bufi][rr * STRK + cc * 4]),                         \
                  &Kg[kvbase + (size_t)((jt) * 64 + rr) * D_ + cc * 4]);       \
        }                                                                      \
    }
#define VSTAGE(jt, bufi)                                                       \
    {                                                                          \
        _Pragma("unroll")                                                      \
        for (int r = 0; r < 4; r++) {                                          \
            int idx = tid + r * 256, rr = idx >> 4, cc = idx & 15;             \
            cpa16(cvs(&Vsb[bufi][rr * STRV + cc * 4]),                         \
                  &Vg[kvbase + (size_t)((jt) * 64 + rr) * D_ + cc * 4]);       \
        }                                                                      \
    }

    // stage Q (tf32, scaled, head-dim permuted); pull A-fragments via LDS64
#pragma unroll
    for (int r = 0; r < 4; r++) {
        int idx = tid + r * 256, rr = idx >> 4, cc = idx & 15;
        *(float4*)&Qs[rr * STRK + cc * 4] =
            *(const float4*)&Qg[qbase + (size_t)rr * D_ + cc * 4];
    }
    __syncthreads();
    uint32_t qa[2][8][4];
#pragma unroll
    for (int mm = 0; mm < 2; mm++) {
        int ar = (mw * 32 + mm * 16 + g) * STRK + 2 * t;
#pragma unroll
        for (int k8 = 0; k8 < 8; k8++) {
            uint2 q02 = *(const uint2*)&Qu[ar + 8 * k8];
            uint2 q13 = *(const uint2*)&Qu[ar + 8 * STRK + 8 * k8];
            qa[mm][k8][0] = q02.x; qa[mm][k8][1] = q13.x;
            qa[mm][k8][2] = q02.y; qa[mm][k8][3] = q13.y;
        }
    }

    // ---------------- pass 1: rowsums of exp(scores) ----------------
    KSTAGE(0, 0); CPCOMMIT;
    float ls[2][2] = {};
    for (int jt = 0; jt < S_ / 64; jt++) {
        CPWAIT0;
        __syncthreads();
        if (jt + 1 < S_ / 64) { KSTAGE(jt + 1, (jt + 1) & 1); CPCOMMIT; }
        const uint32_t* Ku = (const uint32_t*)Ksb[jt & 1];
        float c[2][2][4] = {};
#pragma unroll
        for (int k8 = 0; k8 < 8; k8++) {
#pragma unroll
            for (int nf = 0; nf < 2; nf++) {
                int br = (nw * 16 + nf * 8 + g) * STRK + 2 * t + 8 * k8;
                uint2 bb = *(const uint2*)&Ku[br];
                mma8(c[0][nf], qa[0][k8], bb.x, bb.y);
                mma8(c[1][nf], qa[1][k8], bb.x, bb.y);
            }
        }
#pragma unroll
        for (int mm = 0; mm < 2; mm++)
#pragma unroll
            for (int nf = 0; nf < 2; nf++) {
                ls[mm][0] += __expf(c[mm][nf][0]) + __expf(c[mm][nf][1]);
                ls[mm][1] += __expf(c[mm][nf][2]) + __expf(c[mm][nf][3]);
            }
    }
#pragma unroll
    for (int mm = 0; mm < 2; mm++)
#pragma unroll
        for (int hh = 0; hh < 2; hh++) {
            ls[mm][hh] += __shfl_xor_sync(~0u, ls[mm][hh], 1);
            ls[mm][hh] += __shfl_xor_sync(~0u, ls[mm][hh], 2);
        }
    if (t == 0) {
#pragma unroll
        for (int mm = 0; mm < 2; mm++) {
            Ls[nw * 64 + mw * 32 + mm * 16 + g]     = ls[mm][0];
            Ls[nw * 64 + mw * 32 + mm * 16 + 8 + g] = ls[mm][1];
        }
    }
    KSTAGE(0, 0); VSTAGE(0, 0); CPCOMMIT;
    __syncthreads();
    float linv[2][2];
#pragma unroll
    for (int mm = 0; mm < 2; mm++) {
        int r0 = mw * 32 + mm * 16 + g;
        linv[mm][0] = 1.f / (Ls[r0] + Ls[64 + r0] + Ls[128 + r0] + Ls[192 + r0]);
        int r1 = r0 + 8;
        linv[mm][1] = 1.f / (Ls[r1] + Ls[64 + r1] + Ls[128 + r1] + Ls[192 + r1]);
    }
    __syncthreads();  // Qs fragments consumed; PT region now owned by pass 2

    // ---------------- pass 2: P out + P@V ----------------
    float out[2][2][4] = {};
    for (int jt = 0; jt < S_ / 64; jt++) {
        CPWAIT0;
        __syncthreads();
        if (jt + 1 < S_ / 64) {
            KSTAGE(jt + 1, (jt + 1) & 1); VSTAGE(jt + 1, (jt + 1) & 1); CPCOMMIT;
        }
        const uint32_t* Ku = (const uint32_t*)Ksb[jt & 1];
        const uint32_t* Vu = (const uint32_t*)Vsb[jt & 1];
        float c[2][2][4] = {};
#pragma unroll
        for (int k8 = 0; k8 < 8; k8++) {
#pragma unroll
            for (int nf = 0; nf < 2; nf++) {
                int br = (nw * 16 + nf * 8 + g) * STRK + 2 * t + 8 * k8;
                uint2 bb = *(const uint2*)&Ku[br];
                mma8(c[0][nf], qa[0][k8], bb.x, bb.y);
                mma8(c[1][nf], qa[1][k8], bb.x, bb.y);
            }
        }
        // normalized P -> gmem (streaming); tf32 P -> transposed smem tile
#pragma unroll
        for (int mm = 0; mm < 2; mm++) {
            int rowg = mw * 32 + mm * 16 + g;
            int pi = 16 * mw + 8 * mm + g;
            size_t gp = ((size_t)(b * H_ + h) * S_ + (q0 + rowg)) * S_ +
                        jt * 64 + nw * 16 + 2 * t;
#pragma unroll
            for (int nf = 0; nf < 2; nf++) {
                float p0 = __expf(c[mm][nf][0]) * linv[mm][0];
                float p1 = __expf(c[mm][nf][1]) * linv[mm][0];
                float p2 = __expf(c[mm][nf][2]) * linv[mm][1];
                float p3 = __expf(c[mm][nf][3]) * linv[mm][1];
                __stcs((float2*)&Pout[gp + nf * 8], make_float2(p0, p1));
                __stcs((float2*)&Pout[gp + nf * 8 + (size_t)8 * S_],
                       make_float2(p2, p3));
                int c0 = nw * 16 + nf * 8 + 2 * t;
                PT[c0 * 36 + pi] = make_uint2(f2tf(p0), f2tf(p2));
                PT[(c0 + 1) * 36 + pi] = make_uint2(f2tf(p1), f2tf(p3));
            }
        }
        __syncthreads();
        // P @ V  (pa via conflict-free LDS64)
#pragma unroll
        for (int k8 = 0; k8 < 8; k8++) {
            int ca = t + 8 * k8, cb = ca + 4;
            uint2 u0 = PT[ca * 36 + 16 * mw + g];
            uint2 u1 = PT[cb * 36 + 16 * mw + g];
            uint2 u2 = PT[ca * 36 + 16 * mw + 8 + g];
            uint2 u3 = PT[cb * 36 + 16 * mw + 8 + g];
            uint32_t pa0[4] = { u0.x, u0.y, u1.x, u1.y };
            uint32_t pa1[4] = { u2.x, u2.y, u3.x, u3.y };
#pragma unroll
            for (int nf = 0; nf < 2; nf++) {
                int n = nw * 16 + nf * 8 + g;
                uint32_t b0 = Vu[(8 * k8 + t) * STRV + n];
                uint32_t b1 = Vu[(8 * k8 + t + 4) * STRV + n];
                mma8(out[0][nf], pa0, b0, b1);
                mma8(out[1][nf], pa1, b0, b1);
            }
        }
        __syncthreads();
    }

    // epilogue: AO in [B,S,D], tf32-rounded for the O-GEMM (unpermuted)
#pragma unroll
    for (int mm = 0; mm < 2; mm++) {
        int row = q0 + mw * 32 + mm * 16 + g;
#pragma unroll
        for (int nf = 0; nf < 2; nf++) {
            int dk = h * DK_ + nw * 16 + nf * 8 + 2 * t;
            *(float2*)&Oout[((size_t)b * S_ + row) * D_ + dk] =
                make_float2(__uint_as_float(f2tf(out[mm][nf][0])),
                            __uint_as_float(f2tf(out[mm][nf][1])));
            *(float2*)&Oout[((size_t)b * S_ + row + 8) * D_ + dk] =
                make_float2(__uint_as_float(f2tf(out[mm][nf][2])),
                            __uint_as_float(f2tf(out[mm][nf][3])));
        }
    }
}

// ---------------------------------------------------------------------------
extern "C" void kernel_launch(void* const* d_in, const int* in_sizes, int n_in,
                              void* d_out, int out_size) {
    const float* query = (const float*)d_in[0];
    const float* key   = (const float*)d_in[1];
    const float* value = (const float*)d_in[2];
    const float* Wq = (const float*)d_in[3];
    const float* bq = (const float*)d_in[4];
    const float* Wk = (const float*)d_in[5];
    const float* bk = (const float*)d_in[6];
    const float* Wv = (const float*)d_in[7];
    const float* bv = (const float*)d_in[8];
    const float* Wo = (const float*)d_in[9];
    const float* bo = (const float*)d_in[10];

    float* out_main = (float*)d_out;
    float* out_attn = (float*)d_out + (size_t)B_ * S_ * D_;

    float* Qp;  cudaGetSymbolAddress((void**)&Qp, g_Q);
    float* Kp;  cudaGetSymbolAddress((void**)&Kp, g_K);
    float* Vp;  cudaGetSymbolAddress((void**)&Vp, g_V);
    float* AOp; cudaGetSymbolAddress((void**)&AOp, g_AO);
    float* Tp;  cudaGetSymbolAddress((void**)&Tp, g_T);
    float* Wp;  cudaGetSymbolAddress((void**)&Wp, g_W4);

    const size_t NX = (size_t)B_ * S_ * D_;   // 6291456
    const size_t NW = (size_t)D_ * D_;        // 589824

    preround3<<<dim3((int)(NX / 8 + 255) / 256, 3), 256>>>(
        query, key, value, Tp, (int)(NX / 8));
    preround4<<<dim3((int)(NW / 8 + 255) / 256, 4), 256>>>(
        Wq, Wk, Wv, Wo, Wp, (int)(NW / 8));

    const int M = B_ * S_;
    const int qsmem = (2 * 128 * GSTR + 2 * 64 * GSTR) * 4;   // 61440 B
    cudaFuncSetAttribute(gemm_qkv,
                         cudaFuncAttributeMaxDynamicSharedMemorySize, qsmem);
    const int osmem = (2 * 8704 + 2 * 4352) * 4;              // 104448 B
    cudaFuncSetAttribute(gemm_o,
                         cudaFuncAttributeMaxDynamicSharedMemorySize, osmem);
    const int asmem = (2 * 64 * STRK + 2 * 64 * STRV + 4608 + 256) * 4;  // 93184 B
    cudaFuncSetAttribute(attn_tc,
                         cudaFuncAttributeMaxDynamicSharedMemorySize, asmem);

    gemm_qkv<<<dim3(M / 128, D_ / 64, 3), 256, qsmem>>>(
        Tp, Wp, bq, bk, bv, Qp, Kp, Vp);

    attn_tc<<<dim3(S_ / 64, H_, B_), 256, asmem>>>(Qp, Kp, Vp, out_attn, AOp);

    gemm_o<<<dim3(M / 128, D_ / 64), 256, osmem>>>(
        AOp, Wp + 3 * NW, bo, out_main, M, D_, D_);
}